// round 14
// baseline (speedup 1.0000x reference)
#include <cuda_runtime.h>
#include <mma.h>
#include <math.h>
#include <stdint.h>

using namespace nvcuda;

// Problem constants (fixed shapes)
#define T_TOK 4096           // B*S tokens
#define DDIM  1024           // embed dim
#define UDIM  4096           // hidden dim
#define NEXP  8              // experts
#define NSLOT (T_TOK * 2)    // token-slot = (token<<1)|k

// Scratch in device globals (no allocations allowed in kernel_launch)
__device__ float g_h[(size_t)NSLOT * UDIM];   // gelu(up) acts, tf32-rounded (134 MB)
__device__ float g_y[(size_t)NSLOT * DDIM];   // weighted down outputs (33.5 MB)
__device__ float g_w[NSLOT];                  // router weight per slot
__device__ int   g_list[NEXP * T_TOK];        // per-expert slot lists
__device__ int   g_count[NEXP];               // per-expert token counts
// tf32-preconverted operands (written every launch; deterministic)
__device__ float g_xt[(size_t)T_TOK * DDIM];              // 16.8 MB
__device__ float g_wut[(size_t)NEXP * UDIM * DDIM];       // 134 MB
__device__ float g_wdt[(size_t)NEXP * DDIM * UDIM];       // 134 MB

// ---------------------------------------------------------------------------
__global__ void init_kernel() {
    if (threadIdx.x < NEXP) g_count[threadIdx.x] = 0;
}

// ---------------------------------------------------------------------------
// Elementwise RNA tf32 rounding into the preconverted buffers.
// sel: 0 -> g_xt, 1 -> g_wut, 2 -> g_wdt
__global__ void tf32_conv(const float4* __restrict__ in, int n4, int sel) {
    int i = blockIdx.x * blockDim.x + threadIdx.x;
    if (i >= n4) return;
    float4* out = (sel == 0) ? (float4*)g_xt
                : (sel == 1) ? (float4*)g_wut
                             : (float4*)g_wdt;
    float4 v = in[i];
    out[i] = make_float4(wmma::__float_to_tf32(v.x), wmma::__float_to_tf32(v.y),
                         wmma::__float_to_tf32(v.z), wmma::__float_to_tf32(v.w));
}

// ---------------------------------------------------------------------------
// Router: one warp per token. Exact fp32 logits, deterministic top-2 with
// lower-index tie-break (matches jax.lax.top_k), softmax over the two logits.
__global__ void router_kernel(const float* __restrict__ x,
                              const float* __restrict__ wr) {
    int gw   = (blockIdx.x * blockDim.x + threadIdx.x) >> 5;
    int lane = threadIdx.x & 31;
    if (gw >= T_TOK) return;

    const float* xr = x + (size_t)gw * DDIM;
    float xv[32];
#pragma unroll
    for (int i = 0; i < 32; i++) xv[i] = xr[lane + 32 * i];

    float lg[NEXP];
#pragma unroll
    for (int e = 0; e < NEXP; e++) {
        const float* w = wr + (size_t)e * DDIM;
        float s = 0.f;
#pragma unroll
        for (int i = 0; i < 32; i++) s = fmaf(xv[i], w[lane + 32 * i], s);
#pragma unroll
        for (int o = 16; o > 0; o >>= 1) s += __shfl_xor_sync(0xffffffffu, s, o);
        lg[e] = s;
    }

    if (lane == 0) {
        int i0 = 0; float v0 = lg[0];
#pragma unroll
        for (int e = 1; e < NEXP; e++) if (lg[e] > v0) { v0 = lg[e]; i0 = e; }
        int i1 = -1; float v1 = -INFINITY;
#pragma unroll
        for (int e = 0; e < NEXP; e++)
            if (e != i0 && lg[e] > v1) { v1 = lg[e]; i1 = e; }

        float e1 = expf(v1 - v0);
        float s  = 1.f + e1;

        int p0 = atomicAdd(&g_count[i0], 1);
        g_list[i0 * T_TOK + p0] = (gw << 1);
        g_w[gw * 2 + 0] = 1.f / s;

        int p1 = atomicAdd(&g_count[i1], 1);
        g_list[i1 * T_TOK + p1] = (gw << 1) | 1;
        g_w[gw * 2 + 1] = e1 / s;
    }
}

// ---------------------------------------------------------------------------
// cp.async helpers
__device__ __forceinline__ uint32_t smem_u32(const void* p) {
    uint32_t a;
    asm("{ .reg .u64 t; cvta.to.shared.u64 t, %1; cvt.u32.u64 %0, t; }"
        : "=r"(a) : "l"(p));
    return a;
}
__device__ __forceinline__ void cp16(uint32_t dst, const void* src, uint32_t sz) {
    asm volatile("cp.async.cg.shared.global [%0], [%1], 16, %2;"
                 :: "r"(dst), "l"(src), "r"(sz) : "memory");
}
__device__ __forceinline__ void cp_commit() {
    asm volatile("cp.async.commit_group;" ::: "memory");
}
template <int N>
__device__ __forceinline__ void cp_wait() {
    asm volatile("cp.async.wait_group %0;" :: "n"(N) : "memory");
}

// ---------------------------------------------------------------------------
// Grouped GEMM, TF32 wmma, cp.async 3-stage pipeline, BK=32.
// Block tile 128x256, 512 threads (16 warps), warp tile 32x64.
// Operands are PRE-ROUNDED to tf32 (g_xt/g_h and g_wut/g_wdt).
// C[M_e, NDIM] = A[M_e, KDIM] * W_e[NDIM, KDIM]^T
// IS_UP:   A = g_xt rows (slot>>1); epilogue bias + exact GELU -> g_h (tf32-rounded)
// !IS_UP:  A = g_h rows (slot);     epilogue bias * router weight -> g_y (fp32)
#define BM   128
#define BLKN 256
#define BK2  32
#define LDT  36                                   // 32 + 4 pad floats per row
#define A_FLOATS (BM * LDT)                       // 4608
#define STAGE_FLOATS ((BM + BLKN) * LDT)          // 13824 floats = 55296 B
#define NSTG 3
#define SMEM_DYN (NSTG * STAGE_FLOATS * 4)        // 165888 B
#define LDC  20                                   // epilogue scratch stride

template <int NDIM, int KDIM, bool IS_UP>
__global__ __launch_bounds__(512, 1)
void moe_gemm(const float* __restrict__ bias) {
    extern __shared__ float dsm[];
    __shared__ int srow[BM];

    const int e   = blockIdx.z;
    const int cnt = g_count[e];
    const int m0  = blockIdx.y * BM;
    if (m0 >= cnt) return;
    const int n0  = blockIdx.x * BLKN;
    const int tid = threadIdx.x;
    const int warp = tid >> 5;
    const int lane = tid & 31;

    if (tid < BM) {
        int r = m0 + tid;
        srow[tid] = (r < cnt) ? g_list[e * T_TOK + r] : -1;
    }
    __syncthreads();

    const float* W = (IS_UP ? &g_wut[0] : &g_wdt[0]) + (size_t)e * NDIM * KDIM;
    const uint32_t sbase = smem_u32(dsm);

    // ---- cp.async geometry ----------------------------------------------
    // A tile: 128 rows x 32 floats = 1024 16B-chunks; 2 per thread.
    const float* aSrc[2];
    uint32_t     aSz[2], dA[2];
#pragma unroll
    for (int it = 0; it < 2; it++) {
        int c  = tid + it * 512;
        int r  = c >> 3;          // row 0..127
        int cc = c & 7;           // 16B chunk in row
        int slot = srow[r];
        aSz[it] = (slot < 0) ? 0u : 16u;
        aSrc[it] = (slot < 0) ? (const float*)&g_xt[0]
                 : (IS_UP ? (&g_xt[0] + (size_t)(slot >> 1) * KDIM + cc * 4)
                          : (&g_h[0]  + (size_t)slot * KDIM + cc * 4));
        dA[it] = (uint32_t)(r * LDT + cc * 4) * 4u;
    }
    // B tile: 256 rows x 32 floats = 2048 chunks; 4 per thread.
    const float* bSrc[4];
    uint32_t     dB[4];
#pragma unroll
    for (int it = 0; it < 4; it++) {
        int c  = tid + it * 512;
        int r  = c >> 3;          // row 0..255
        int cc = c & 7;
        bSrc[it] = W + (size_t)(n0 + r) * KDIM + cc * 4;
        dB[it] = (uint32_t)(A_FLOATS + r * LDT + cc * 4) * 4u;
    }

    auto ISSUE = [&](int stage, int k0) {
        uint32_t sb = sbase + (uint32_t)stage * (STAGE_FLOATS * 4u);
#pragma unroll
        for (int it = 0; it < 2; it++) cp16(sb + dA[it], aSrc[it] + k0, aSz[it]);
#pragma unroll
        for (int it = 0; it < 4; it++) cp16(sb + dB[it], bSrc[it] + k0, 16u);
        cp_commit();
    };

    // Warp tile: 32 rows x 64 cols. 4x4 warp grid over 128x256.
    const int wm = warp & 3;
    const int wn = warp >> 2;

    wmma::fragment<wmma::accumulator, 16, 16, 8, float> fc[2][4];
#pragma unroll
    for (int i = 0; i < 2; i++)
#pragma unroll
        for (int j = 0; j < 4; j++) wmma::fill_fragment(fc[i][j], 0.f);

    constexpr int KT = KDIM / BK2;

    // Prologue: stages 0 and 1 in flight
    ISSUE(0, 0);
    ISSUE(1, BK2);

    for (int kt = 0; kt < KT; kt++) {
        if (kt == KT - 1) cp_wait<0>(); else cp_wait<1>();
        __syncthreads();
        if (kt + 2 < KT) ISSUE((kt + 2) % NSTG, (kt + 2) * BK2);

        const float* sA = dsm + (kt % NSTG) * STAGE_FLOATS;
        const float* sB = sA + A_FLOATS;
#pragma unroll
        for (int kk = 0; kk < BK2; kk += 8) {
            wmma::fragment<wmma::matrix_a, 16, 16, 8, wmma::precision::tf32,
                           wmma::row_major> fa[2];
            wmma::fragment<wmma::matrix_b, 16, 16, 8, wmma::precision::tf32,
                           wmma::col_major> fb[4];
#pragma unroll
            for (int i = 0; i < 2; i++)
                wmma::load_matrix_sync(fa[i], sA + (wm * 32 + i * 16) * LDT + kk, LDT);
#pragma unroll
            for (int j = 0; j < 4; j++)
                wmma::load_matrix_sync(fb[j], sB + (wn * 64 + j * 16) * LDT + kk, LDT);
#pragma unroll
            for (int i = 0; i < 2; i++)
#pragma unroll
                for (int j = 0; j < 4; j++)
                    wmma::mma_sync(fc[i][j], fa[i], fb[j], fc[i][j]);
        }
    }
    __syncthreads();   // all mma done before scratch overlay

    // ---- epilogue: per-warp private scratch, one 16x16 fragment at a time.
    float* scratch = dsm + warp * (16 * LDC);
    const int rbase = lane >> 4;
    const int c     = lane & 15;

#pragma unroll
    for (int i = 0; i < 2; i++) {
#pragma unroll
        for (int j = 0; j < 4; j++) {
            wmma::store_matrix_sync(scratch, fc[i][j], LDC, wmma::mem_row_major);
            __syncwarp();
            const int colg = n0 + wn * 64 + j * 16 + c;
            const float bval = bias[(size_t)e * NDIM + colg];
#pragma unroll
            for (int rr = 0; rr < 8; rr++) {
                int rl   = rr * 2 + rbase;
                int row  = wm * 32 + i * 16 + rl;
                int slot = srow[row];
                if (slot < 0) continue;
                float v = scratch[rl * LDC + c] + bval;
                if (IS_UP) {
                    v = 0.5f * v * (1.f + erff(v * 0.70710678118654752f));
                    // store pre-rounded for the down GEMM (same bits as staging cvt)
                    g_h[(size_t)slot * UDIM + colg] = wmma::__float_to_tf32(v);
                } else {
                    g_y[(size_t)slot * DDIM + colg] = v * g_w[slot];
                }
            }
            __syncwarp();
        }
    }
}

// ---------------------------------------------------------------------------
// out[t,d] = y[slot=2t] + y[slot=2t+1]   (fixed order -> deterministic)
__global__ void combine_kernel(float* __restrict__ out) {
    int i = blockIdx.x * blockDim.x + threadIdx.x;
    if (i >= T_TOK * DDIM) return;
    int t = i >> 10;
    int d = i & (DDIM - 1);
    out[i] = g_y[(size_t)(2 * t) * DDIM + d] +
             g_y[(size_t)(2 * t + 1) * DDIM + d];
}

// ---------------------------------------------------------------------------
extern "C" void kernel_launch(void* const* d_in, const int* in_sizes, int n_in,
                              void* d_out, int out_size) {
    const float* x  = (const float*)d_in[0];
    const float* wr = (const float*)d_in[1];
    const float* wu = (const float*)d_in[2];
    const float* bu = (const float*)d_in[3];
    const float* wd = (const float*)d_in[4];
    const float* bd = (const float*)d_in[5];
    float* out = (float*)d_out;

    cudaFuncSetAttribute(moe_gemm<UDIM, DDIM, true>,
                         cudaFuncAttributeMaxDynamicSharedMemorySize, SMEM_DYN);
    cudaFuncSetAttribute(moe_gemm<DDIM, UDIM, false>,
                         cudaFuncAttributeMaxDynamicSharedMemorySize, SMEM_DYN);

    init_kernel<<<1, 32>>>();

    const int n4x = T_TOK * DDIM / 4;                 // 1,048,576
    const int n4w = NEXP * UDIM * DDIM / 4;           // 8,388,608
    tf32_conv<<<(n4x + 255) / 256, 256>>>((const float4*)x,  n4x, 0);
    tf32_conv<<<(n4w + 255) / 256, 256>>>((const float4*)wu, n4w, 1);
    tf32_conv<<<(n4w + 255) / 256, 256>>>((const float4*)wd, n4w, 2);

    router_kernel<<<(T_TOK * 32) / 256, 256>>>(x, wr);

    dim3 gu(UDIM / BLKN, T_TOK / BM, NEXP);   // (16, 32, 8)
    moe_gemm<UDIM, DDIM, true><<<gu, 512, SMEM_DYN>>>(bu);

    dim3 gd(DDIM / BLKN, T_TOK / BM, NEXP);   // (4, 32, 8)
    moe_gemm<DDIM, UDIM, false><<<gd, 512, SMEM_DYN>>>(bd);

    combine_kernel<<<(T_TOK * DDIM + 255) / 256, 256>>>(out);
}

// round 15
// speedup vs baseline: 1.3924x; 1.3924x over previous
#include <cuda_runtime.h>
#include <mma.h>
#include <math.h>
#include <stdint.h>

using namespace nvcuda;

// Problem constants (fixed shapes)
#define T_TOK 4096           // B*S tokens
#define DDIM  1024           // embed dim
#define UDIM  4096           // hidden dim
#define NEXP  8              // experts
#define NSLOT (T_TOK * 2)    // token-slot = (token<<1)|k

// Scratch in device globals (no allocations allowed in kernel_launch)
__device__ float g_h[(size_t)NSLOT * UDIM];   // gelu(up) acts, tf32-rounded
__device__ float g_y[(size_t)NSLOT * DDIM];   // weighted down outputs
__device__ float g_w[NSLOT];                  // router weight per slot
__device__ int   g_list[NEXP * T_TOK];        // per-expert slot lists
__device__ int   g_count[NEXP];               // per-expert token counts
// tf32-preconverted operands (written every launch; deterministic)
__device__ float g_xt[(size_t)T_TOK * DDIM];
__device__ float g_wut[(size_t)NEXP * UDIM * DDIM];
__device__ float g_wdt[(size_t)NEXP * DDIM * UDIM];

// ---------------------------------------------------------------------------
__global__ void init_kernel() {
    if (threadIdx.x < NEXP) g_count[threadIdx.x] = 0;
}

// ---------------------------------------------------------------------------
// Elementwise RNA tf32 rounding into the preconverted buffers.
__global__ void tf32_conv(const float4* __restrict__ in, int n4, int sel) {
    int i = blockIdx.x * blockDim.x + threadIdx.x;
    if (i >= n4) return;
    float4* out = (sel == 0) ? (float4*)g_xt
                : (sel == 1) ? (float4*)g_wut
                             : (float4*)g_wdt;
    float4 v = in[i];
    out[i] = make_float4(wmma::__float_to_tf32(v.x), wmma::__float_to_tf32(v.y),
                         wmma::__float_to_tf32(v.z), wmma::__float_to_tf32(v.w));
}

// ---------------------------------------------------------------------------
// Router: one warp per token. Exact fp32 logits, deterministic top-2 with
// lower-index tie-break (matches jax.lax.top_k), softmax over the two logits.
__global__ void router_kernel(const float* __restrict__ x,
                              const float* __restrict__ wr) {
    int gw   = (blockIdx.x * blockDim.x + threadIdx.x) >> 5;
    int lane = threadIdx.x & 31;
    if (gw >= T_TOK) return;

    const float* xr = x + (size_t)gw * DDIM;
    float xv[32];
#pragma unroll
    for (int i = 0; i < 32; i++) xv[i] = xr[lane + 32 * i];

    float lg[NEXP];
#pragma unroll
    for (int e = 0; e < NEXP; e++) {
        const float* w = wr + (size_t)e * DDIM;
        float s = 0.f;
#pragma unroll
        for (int i = 0; i < 32; i++) s = fmaf(xv[i], w[lane + 32 * i], s);
#pragma unroll
        for (int o = 16; o > 0; o >>= 1) s += __shfl_xor_sync(0xffffffffu, s, o);
        lg[e] = s;
    }

    if (lane == 0) {
        int i0 = 0; float v0 = lg[0];
#pragma unroll
        for (int e = 1; e < NEXP; e++) if (lg[e] > v0) { v0 = lg[e]; i0 = e; }
        int i1 = -1; float v1 = -INFINITY;
#pragma unroll
        for (int e = 0; e < NEXP; e++)
            if (e != i0 && lg[e] > v1) { v1 = lg[e]; i1 = e; }

        float e1 = expf(v1 - v0);
        float s  = 1.f + e1;

        int p0 = atomicAdd(&g_count[i0], 1);
        g_list[i0 * T_TOK + p0] = (gw << 1);
        g_w[gw * 2 + 0] = 1.f / s;

        int p1 = atomicAdd(&g_count[i1], 1);
        g_list[i1 * T_TOK + p1] = (gw << 1) | 1;
        g_w[gw * 2 + 1] = e1 / s;
    }
}

// ---------------------------------------------------------------------------
// Grouped GEMM, TF32 wmma, 2-stage register-prefetch pipeline (R5-proven
// skeleton), PRE-ROUNDED operands (no in-loop cvt), both kk-groups' fragments
// loaded up front for tensor-pipe ILP.
// C[M_e, NDIM] = A[M_e, KDIM] * W_e[NDIM, KDIM]^T
// IS_UP:   A = g_xt rows (slot>>1); epilogue bias + exact GELU -> g_h (tf32-rounded)
// !IS_UP:  A = g_h rows (slot);     epilogue bias * router weight -> g_y (fp32)
#define BM 128
#define BN 64
#define BK 16
#define LDT (BK + 4)   // 20 floats
#define LDC (BN + 4)   // 68 floats
#define BUF_FLOATS (BM * LDT + BN * LDT)   // 3840 floats per stage

template <int NDIM, int KDIM, bool IS_UP>
__global__ __launch_bounds__(256, 2)
void moe_gemm(const float* __restrict__ bias) {
    // Two pipeline buffers (2*3840) overlaid inside the C-tile region (8704).
    __shared__ float smem[BM * LDC];
    __shared__ int   srow[BM];

    const int e   = blockIdx.z;
    const int cnt = g_count[e];
    const int m0  = blockIdx.y * BM;
    if (m0 >= cnt) return;
    const int n0  = blockIdx.x * BN;
    const int tid = threadIdx.x;

    if (tid < BM) {
        int r = m0 + tid;
        srow[tid] = (r < cnt) ? g_list[e * T_TOK + r] : -1;
    }
    __syncthreads();

    const float* W = (IS_UP ? &g_wut[0] : &g_wdt[0]) + (size_t)e * NDIM * KDIM;

    // ---- loop-invariant staging geometry ---------------------------------
    // A tile: 128 rows x 16 cols = 512 float4; 2 per thread (gathered rows).
    const float* aptr[2];
    int          offA[2];
#pragma unroll
    for (int it = 0; it < 2; it++) {
        int f4 = tid + it * 256;
        int r  = f4 >> 2;
        int c4 = f4 & 3;
        int slot = srow[r];
        aptr[it] = (slot < 0) ? nullptr
                 : (IS_UP ? (&g_xt[0] + (size_t)(slot >> 1) * KDIM + c4 * 4)
                          : (&g_h[0]  + (size_t)slot * KDIM + c4 * 4));
        offA[it] = r * LDT + c4 * 4;
    }
    // B tile: 64 rows x 16 cols = 256 float4; 1 per thread.
    const float* bptr = W + (size_t)(n0 + (tid >> 2)) * KDIM + (tid & 3) * 4;
    const int    offB = BM * LDT + (tid >> 2) * LDT + (tid & 3) * 4;

    float4 ra[2], rbv;
    auto LOAD = [&](int k0) {
#pragma unroll
        for (int it = 0; it < 2; it++)
            ra[it] = aptr[it] ? *reinterpret_cast<const float4*>(aptr[it] + k0)
                              : make_float4(0.f, 0.f, 0.f, 0.f);
        rbv = *reinterpret_cast<const float4*>(bptr + k0);
    };
    auto STORE = [&](float* base) {   // pure copy: operands pre-rounded
#pragma unroll
        for (int it = 0; it < 2; it++)
            *reinterpret_cast<float4*>(base + offA[it]) = ra[it];
        *reinterpret_cast<float4*>(base + offB) = rbv;
    };

    wmma::fragment<wmma::accumulator, 16, 16, 8, float> fc[2][2];
#pragma unroll
    for (int i = 0; i < 2; i++)
#pragma unroll
        for (int j = 0; j < 2; j++) wmma::fill_fragment(fc[i][j], 0.f);

    const int warp = tid >> 5;
    const int wm   = warp & 3;    // 0..3 -> 32-row slab
    const int wn   = warp >> 2;   // 0..1 -> 32-col slab

    float* buf[2] = { smem, smem + BUF_FLOATS };
    constexpr int KT = KDIM / BK;

    // Prologue: fill stage 0
    LOAD(0);
    STORE(buf[0]);
    __syncthreads();

    for (int kt = 0; kt < KT; kt++) {
        // Prefetch next k-tile into registers (covered by mma below)
        if (kt + 1 < KT) LOAD((kt + 1) * BK);

        const float* sA = buf[kt & 1];
        const float* sB = buf[kt & 1] + BM * LDT;

        // Load BOTH kk-groups' fragments up front, then issue all 16 mmas:
        // group-1 LDS latency hides under group-0 mmas.
        wmma::fragment<wmma::matrix_a, 16, 16, 8, wmma::precision::tf32,
                       wmma::row_major> fa[2][2];
        wmma::fragment<wmma::matrix_b, 16, 16, 8, wmma::precision::tf32,
                       wmma::col_major> fb[2][2];
#pragma unroll
        for (int g = 0; g < 2; g++) {
#pragma unroll
            for (int i = 0; i < 2; i++)
                wmma::load_matrix_sync(fa[g][i],
                    sA + (wm * 32 + i * 16) * LDT + g * 8, LDT);
#pragma unroll
            for (int j = 0; j < 2; j++)
                wmma::load_matrix_sync(fb[g][j],
                    sB + (wn * 32 + j * 16) * LDT + g * 8, LDT);
        }
#pragma unroll
        for (int g = 0; g < 2; g++)
#pragma unroll
            for (int i = 0; i < 2; i++)
#pragma unroll
                for (int j = 0; j < 2; j++)
                    wmma::mma_sync(fc[i][j], fa[g][i], fb[g][j], fc[i][j]);

        // Refill the other stage, then one barrier per iteration.
        if (kt + 1 < KT) STORE(buf[(kt + 1) & 1]);
        __syncthreads();
    }

    // ---- epilogue: park accumulators in smem, coalesced elementwise pass -
#pragma unroll
    for (int i = 0; i < 2; i++)
#pragma unroll
        for (int j = 0; j < 2; j++)
            wmma::store_matrix_sync(smem + (wm * 32 + i * 16) * LDC + wn * 32 + j * 16,
                                    fc[i][j], LDC, wmma::mem_row_major);
    __syncthreads();

    const int c  = tid & (BN - 1);
    const int rb = tid >> 6;   // 0..3
    const float bcol = bias[(size_t)e * NDIM + n0 + c];
#pragma unroll 4
    for (int r = rb; r < BM; r += 4) {
        int slot = srow[r];
        if (slot < 0) continue;
        float v = smem[r * LDC + c] + bcol;
        if (IS_UP) {
            // exact GELU: 0.5*x*(1+erf(x/sqrt(2)))
            v = 0.5f * v * (1.f + erff(v * 0.70710678118654752f));
            // store pre-rounded for the down GEMM (same bits as staging cvt)
            g_h[(size_t)slot * UDIM + n0 + c] = wmma::__float_to_tf32(v);
        } else {
            g_y[(size_t)slot * DDIM + n0 + c] = v * g_w[slot];
        }
    }
}

// ---------------------------------------------------------------------------
// out[t,d] = y[slot=2t] + y[slot=2t+1]   (fixed order -> deterministic)
__global__ void combine_kernel(float* __restrict__ out) {
    int i = blockIdx.x * blockDim.x + threadIdx.x;
    if (i >= T_TOK * DDIM) return;
    int t = i >> 10;
    int d = i & (DDIM - 1);
    out[i] = g_y[(size_t)(2 * t) * DDIM + d] +
             g_y[(size_t)(2 * t + 1) * DDIM + d];
}

// ---------------------------------------------------------------------------
extern "C" void kernel_launch(void* const* d_in, const int* in_sizes, int n_in,
                              void* d_out, int out_size) {
    const float* x  = (const float*)d_in[0];
    const float* wr = (const float*)d_in[1];
    const float* wu = (const float*)d_in[2];
    const float* bu = (const float*)d_in[3];
    const float* wd = (const float*)d_in[4];
    const float* bd = (const float*)d_in[5];
    float* out = (float*)d_out;

    init_kernel<<<1, 32>>>();

    const int n4x = T_TOK * DDIM / 4;
    const int n4w = NEXP * UDIM * DDIM / 4;
    tf32_conv<<<(n4x + 255) / 256, 256>>>((const float4*)x,  n4x, 0);
    tf32_conv<<<(n4w + 255) / 256, 256>>>((const float4*)wu, n4w, 1);
    tf32_conv<<<(n4w + 255) / 256, 256>>>((const float4*)wd, n4w, 2);

    router_kernel<<<(T_TOK * 32) / 256, 256>>>(x, wr);

    dim3 gu(UDIM / BN, T_TOK / BM, NEXP);   // (64, 32, 8)
    moe_gemm<UDIM, DDIM, true><<<gu, 256>>>(bu);

    dim3 gd(DDIM / BN, T_TOK / BM, NEXP);   // (16, 32, 8)
    moe_gemm<DDIM, UDIM, false><<<gd, 256>>>(bd);

    combine_kernel<<<(T_TOK * DDIM + 255) / 256, 256>>>(out);
}